// round 6
// baseline (speedup 1.0000x reference)
#include <cuda_runtime.h>
#include <cstdint>

#define BSZ 2048
#define LSZ 512
#define DSZ 128

__device__ int g_len[BSZ];     // normalized lengths (dtype auto-detected)
__device__ int g_perm[BSZ];    // batch rows sorted by descending length

#define WARP_RED_SUM(p)                                   \
    p += __shfl_xor_sync(0xffffffffu, p, 16);             \
    p += __shfl_xor_sync(0xffffffffu, p, 8);              \
    p += __shfl_xor_sync(0xffffffffu, p, 4);              \
    p += __shfl_xor_sync(0xffffffffu, p, 2);              \
    p += __shfl_xor_sync(0xffffffffu, p, 1);

#define WARP_RED_SUM4(a, b, c, d)                         \
    a += __shfl_xor_sync(0xffffffffu, a, 16);             \
    b += __shfl_xor_sync(0xffffffffu, b, 16);             \
    c += __shfl_xor_sync(0xffffffffu, c, 16);             \
    d += __shfl_xor_sync(0xffffffffu, d, 16);             \
    a += __shfl_xor_sync(0xffffffffu, a, 8);              \
    b += __shfl_xor_sync(0xffffffffu, b, 8);              \
    c += __shfl_xor_sync(0xffffffffu, c, 8);              \
    d += __shfl_xor_sync(0xffffffffu, d, 8);              \
    a += __shfl_xor_sync(0xffffffffu, a, 4);              \
    b += __shfl_xor_sync(0xffffffffu, b, 4);              \
    c += __shfl_xor_sync(0xffffffffu, c, 4);              \
    d += __shfl_xor_sync(0xffffffffu, d, 4);              \
    a += __shfl_xor_sync(0xffffffffu, a, 2);              \
    b += __shfl_xor_sync(0xffffffffu, b, 2);              \
    c += __shfl_xor_sync(0xffffffffu, c, 2);              \
    d += __shfl_xor_sync(0xffffffffu, d, 2);              \
    a += __shfl_xor_sync(0xffffffffu, a, 1);              \
    b += __shfl_xor_sync(0xffffffffu, b, 1);              \
    c += __shfl_xor_sync(0xffffffffu, c, 1);              \
    d += __shfl_xor_sync(0xffffffffu, d, 1);

__device__ __forceinline__ float dot128(float4 a, float4 b) {
    return fmaf(a.x, b.x, fmaf(a.y, b.y, fmaf(a.z, b.z, a.w * b.w)));
}

__device__ __forceinline__ void cp_async16(uint32_t dst, const float* src) {
    asm volatile("cp.async.cg.shared.global [%0], [%1], 16;"
                 :: "r"(dst), "l"(src) : "memory");
}
#define CP_COMMIT() asm volatile("cp.async.commit_group;" ::: "memory")
#define CP_WAIT6()  asm volatile("cp.async.wait_group 6;" ::: "memory")

// ---------------------------------------------------------------------------
// Setup: (a) normalize `lengths` to int32 with int32/int64 auto-detect
// (int64 values < 512 have all-zero odd int32 words; genuine random int32
// data in [0,512) has P(all 1024 odd words zero) = (1/512)^1024 ~ 0),
// (b) counting-sort rows by DESCENDING length into g_perm (longest rows
// scheduled first -> no straggler tail). Parallel shfl-based block scan.
// ---------------------------------------------------------------------------
__global__ __launch_bounds__(1024) void setup_kernel(const int* __restrict__ Lraw) {
    __shared__ int cnt[LSZ];
    __shared__ int wsum[16];
    __shared__ int s_any;
    int tid  = threadIdx.x;                 // single block, 1024 threads
    int lane = tid & 31;
    if (tid == 0) s_any = 0;
    if (tid < LSZ) cnt[tid] = 0;
    __syncthreads();
    if (Lraw[2 * tid + 1] != 0) s_any = 1;  // benign race
    __syncthreads();
    int l0, l1;
    if (s_any == 0) {                       // int64 layout
        const long long* L64 = (const long long*)Lraw;
        l0 = (int)L64[2 * tid];
        l1 = (int)L64[2 * tid + 1];
    } else {                                // int32 layout
        l0 = Lraw[2 * tid];
        l1 = Lraw[2 * tid + 1];
    }
    g_len[2 * tid]     = l0;
    g_len[2 * tid + 1] = l1;
    atomicAdd(&cnt[l0], 1);
    atomicAdd(&cnt[l1], 1);
    __syncthreads();

    // Descending exclusive scan: thread r (r<512) owns length l = 511-r.
    int val = 0, incl = 0;
    if (tid < LSZ) {
        val  = cnt[LSZ - 1 - tid];
        incl = val;
        #pragma unroll
        for (int d = 1; d < 32; d <<= 1) {
            int t = __shfl_up_sync(0xffffffffu, incl, d);
            if (lane >= d) incl += t;
        }
        if (lane == 31) wsum[tid >> 5] = incl;
    }
    __syncthreads();
    if (tid < 16) {
        int w = wsum[tid];
        int wi = w;
        #pragma unroll
        for (int d = 1; d < 16; d <<= 1) {
            int t = __shfl_up_sync(0x0000ffffu, wi, d);
            if (tid >= d) wi += t;
        }
        wsum[tid] = wi - w;                 // exclusive warp offsets
    }
    __syncthreads();
    if (tid < LSZ) cnt[LSZ - 1 - tid] = (incl - val) + wsum[tid >> 5];
    __syncthreads();

    int p0 = atomicAdd(&cnt[l0], 1); g_perm[p0] = 2 * tid;
    int p1 = atomicAdd(&cnt[l1], 1); g_perm[p1] = 2 * tid + 1;
}

// ---------------------------------------------------------------------------
// Fused kernel: per-CTA q/k/v projection + masked softmax attention over the
// LIVE suffix [512-len, 512) only. One CTA per batch row (via g_perm).
// Phase 1 streams K through a per-warp cp.async ring (zero-register prefetch,
// 7 rows always in flight per warp) so the SHFL reduction latency never
// starves the memory system.
// ---------------------------------------------------------------------------
__global__ __launch_bounds__(256) void attn_kernel(
    const float* __restrict__ x,
    const float* __restrict__ K, const float* __restrict__ V,
    const float* __restrict__ Wq, const float* __restrict__ bq,
    const float* __restrict__ Wk, const float* __restrict__ bk,
    const float* __restrict__ Wv, const float* __restrict__ bv,
    float* __restrict__ out)
{
    __shared__ __align__(16) float xs[DSZ];
    __shared__ __align__(16) float qs[DSZ];
    __shared__ __align__(16) float ks[DSZ];
    __shared__ __align__(16) float vs[DSZ];
    __shared__ __align__(16) float sc[LSZ + 4];
    __shared__ __align__(16) float ring[8][8][DSZ];  // [warp][slot][float] = 32KB
    __shared__ float red[8];
    __shared__ float s_inv;
    // s_part overlays the ring: the ring's last read is in phase 1 (before the
    // phase-2a barrier); s_part is only written in phase 3 (after it).
    float (*s_part)[DSZ] = (float (*)[DSZ])&ring[0][0][0];

    int tid  = threadIdx.x;
    int lane = tid & 31;
    int wid  = tid >> 5;
    int b    = g_perm[blockIdx.x];
    int len  = g_len[b];                // 0 .. 511
    int n    = len + 1;
    int j0   = LSZ - len;
    const float inv_sqrt_d = 0.08838834764831845f;   // 1/sqrt(128)

    size_t base = (size_t)b * LSZ * DSZ;
    const float* Kb = K + base + (size_t)j0 * DSZ;

    // ---- Kick off the K ring BEFORE the projection: 7 rows per warp in
    // flight while we compute q/k/v (free overlap).
    int nr = (len > wid) ? ((len - wid + 7) >> 3) : 0;   // rows i = wid + 8t
    const float* srcw = Kb + (size_t)wid * DSZ + lane * 4;  // lane's 16B chunk
    uint32_t ringw = (uint32_t)__cvta_generic_to_shared(&ring[wid][0][0]) + lane * 16;
    #pragma unroll
    for (int j = 0; j < 7; ++j) {
        if (j < nr) cp_async16(ringw + j * 512, srcw + (size_t)j * 8 * DSZ);
        CP_COMMIT();
    }

    if (tid < 32) ((float4*)xs)[tid] = ((const float4*)(x + (size_t)b * DSZ))[tid];
    __syncthreads();

    // ---- Projection: q[d] = dot(Wq[d,:], x) + bq[d] (same for k,v).
    {
        float4 xv = ((const float4*)xs)[lane];
        #pragma unroll
        for (int m = 0; m < 3; ++m) {
            const float* W    = (m == 0) ? Wq : ((m == 1) ? Wk : Wv);
            const float* bias = (m == 0) ? bq : ((m == 1) ? bk : bv);
            float* dst        = (m == 0) ? qs : ((m == 1) ? ks : vs);
            #pragma unroll
            for (int j = 0; j < 4; ++j) {
                int d0 = wid + 32 * j;
                float4 w0 = ((const float4*)(W + (d0     ) * DSZ))[lane];
                float4 w1 = ((const float4*)(W + (d0 +  8) * DSZ))[lane];
                float4 w2 = ((const float4*)(W + (d0 + 16) * DSZ))[lane];
                float4 w3 = ((const float4*)(W + (d0 + 24) * DSZ))[lane];
                float p0 = dot128(w0, xv);
                float p1 = dot128(w1, xv);
                float p2 = dot128(w2, xv);
                float p3 = dot128(w3, xv);
                WARP_RED_SUM4(p0, p1, p2, p3);
                if (lane == 0) {
                    dst[d0]      = p0 + bias[d0];
                    dst[d0 +  8] = p1 + bias[d0 + 8];
                    dst[d0 + 16] = p2 + bias[d0 + 16];
                    dst[d0 + 24] = p3 + bias[d0 + 24];
                }
            }
        }
    }
    __syncthreads();

    // ---- Phase 1: scores via the cp.async ring. Iter t: wait row t, consume
    // slot t&7, refill slot (t+7)&7 with row t+7. Lane 0 tracks the warp max.
    float wmax = -3.4e38f;
    {
        float4 qv = ((const float4*)qs)[lane];
        for (int t = 0; t < nr; ++t) {
            CP_WAIT6();                              // row t landed (own 16B)
            float4 kv = *(const float4*)&ring[wid][t & 7][lane * 4];
            int tn = t + 7;
            if (tn < nr) cp_async16(ringw + (tn & 7) * 512,
                                    srcw + (size_t)tn * 8 * DSZ);
            CP_COMMIT();
            float p = dot128(kv, qv);
            WARP_RED_SUM(p);
            if (lane == 0) {
                p *= inv_sqrt_d;
                sc[wid + 8 * t] = p;
                wmax = fmaxf(wmax, p);
            }
        }
        if (wid == (len & 7)) {          // the new pushed entry's score
            float4 kn = ((const float4*)ks)[lane];
            float p = dot128(kn, qv);
            WARP_RED_SUM(p);
            if (lane == 0) { p *= inv_sqrt_d; sc[len] = p; wmax = fmaxf(wmax, p); }
        }
        if (lane == 0) red[wid] = wmax;
    }
    __syncthreads();

    // ---- Phase 2a: block max from the 8 per-warp maxima.
    float m = red[0];
    #pragma unroll
    for (int w = 1; w < 8; ++w) m = fmaxf(m, red[w]);
    __syncthreads();                     // protect red[] before reuse for sums

    // ---- Phase 2b: exp + block sum (sc overwritten with p = exp(s-m)).
    float lsum = 0.0f;
    for (int i = tid; i < n; i += 256) {
        float p = __expf(sc[i] - m);
        sc[i] = p;
        lsum += p;
    }
    WARP_RED_SUM(lsum);
    if (lane == 0) red[wid] = lsum;
    __syncthreads();                     // sc (exp'd) and red visible everywhere
    if (tid == 0) {
        float l = 0.0f;
        #pragma unroll
        for (int w = 0; w < 8; ++w) l += red[w];
        s_inv = 1.0f / l;
    }

    // ---- Phase 3: out = (1/l) sum_i p_i V_i. Warp-per-row, float4 accum,
    // 4 rows/iter front-batched (short consume latency keeps MLP~4).
    const float* Vb = V + base + (size_t)j0 * DSZ;
    {
        float4 acc0 = make_float4(0.f, 0.f, 0.f, 0.f);
        float4 acc1 = make_float4(0.f, 0.f, 0.f, 0.f);
        int i = wid;
        for (; i + 24 < len; i += 32) {
            float4 v0 = ((const float4*)(Vb + (size_t)(i     ) * DSZ))[lane];
            float4 v1 = ((const float4*)(Vb + (size_t)(i +  8) * DSZ))[lane];
            float4 v2 = ((const float4*)(Vb + (size_t)(i + 16) * DSZ))[lane];
            float4 v3 = ((const float4*)(Vb + (size_t)(i + 24) * DSZ))[lane];
            float p0 = sc[i], p1 = sc[i + 8], p2 = sc[i + 16], p3 = sc[i + 24];
            acc0.x = fmaf(p0, v0.x, acc0.x); acc1.x = fmaf(p1, v1.x, acc1.x);
            acc0.y = fmaf(p0, v0.y, acc0.y); acc1.y = fmaf(p1, v1.y, acc1.y);
            acc0.z = fmaf(p0, v0.z, acc0.z); acc1.z = fmaf(p1, v1.z, acc1.z);
            acc0.w = fmaf(p0, v0.w, acc0.w); acc1.w = fmaf(p1, v1.w, acc1.w);
            acc0.x = fmaf(p2, v2.x, acc0.x); acc1.x = fmaf(p3, v3.x, acc1.x);
            acc0.y = fmaf(p2, v2.y, acc0.y); acc1.y = fmaf(p3, v3.y, acc1.y);
            acc0.z = fmaf(p2, v2.z, acc0.z); acc1.z = fmaf(p3, v3.z, acc1.z);
            acc0.w = fmaf(p2, v2.w, acc0.w); acc1.w = fmaf(p3, v3.w, acc1.w);
        }
        for (; i < len; i += 8) {
            float4 v0 = ((const float4*)(Vb + (size_t)i * DSZ))[lane];
            float p0 = sc[i];
            acc0.x = fmaf(p0, v0.x, acc0.x);
            acc0.y = fmaf(p0, v0.y, acc0.y);
            acc0.z = fmaf(p0, v0.z, acc0.z);
            acc0.w = fmaf(p0, v0.w, acc0.w);
        }
        if (wid == (len & 7)) {          // the new pushed value
            float4 vn = ((const float4*)vs)[lane];
            float p = sc[len];
            acc0.x = fmaf(p, vn.x, acc0.x);
            acc0.y = fmaf(p, vn.y, acc0.y);
            acc0.z = fmaf(p, vn.z, acc0.z);
            acc0.w = fmaf(p, vn.w, acc0.w);
        }
        acc0.x += acc1.x; acc0.y += acc1.y; acc0.z += acc1.z; acc0.w += acc1.w;
        ((float4*)&s_part[wid][0])[lane] = acc0;   // overlays the (dead) ring
    }
    __syncthreads();                     // also orders s_inv before read below
    if (tid < DSZ) {
        float s = 0.0f;
        #pragma unroll
        for (int w = 0; w < 8; ++w) s += s_part[w][tid];
        out[(size_t)b * DSZ + tid] = s * s_inv;
    }
}

// ---------------------------------------------------------------------------
extern "C" void kernel_launch(void* const* d_in, const int* in_sizes, int n_in,
                              void* d_out, int out_size) {
    const float* inputs      = (const float*)d_in[0];
    const float* prev_keys   = (const float*)d_in[1];
    const float* prev_values = (const float*)d_in[2];
    const float* Wq          = (const float*)d_in[3];
    const float* bq          = (const float*)d_in[4];
    const float* Wk          = (const float*)d_in[5];
    const float* bk          = (const float*)d_in[6];
    const float* Wv          = (const float*)d_in[7];
    const float* bv          = (const float*)d_in[8];
    const int*   lengths_raw = (const int*)d_in[9];
    float* out               = (float*)d_out;

    setup_kernel<<<1, 1024>>>(lengths_raw);
    attn_kernel<<<BSZ, 256>>>(inputs, prev_keys, prev_values,
                              Wq, bq, Wk, bk, Wv, bv, out);
}

// round 7
// speedup vs baseline: 1.0253x; 1.0253x over previous
#include <cuda_runtime.h>
#include <cstdint>

#define BSZ 2048
#define LSZ 512
#define DSZ 128

__device__ int g_len[BSZ];     // normalized lengths (dtype auto-detected)
__device__ int g_perm[BSZ];    // batch rows sorted by descending length

#define WARP_RED_SUM(p)                                   \
    p += __shfl_xor_sync(0xffffffffu, p, 16);             \
    p += __shfl_xor_sync(0xffffffffu, p, 8);              \
    p += __shfl_xor_sync(0xffffffffu, p, 4);              \
    p += __shfl_xor_sync(0xffffffffu, p, 2);              \
    p += __shfl_xor_sync(0xffffffffu, p, 1);

// Two interleaved butterfly trees (pipelines at SHFL issue rate).
#define WARP_RED_SUM2(a, b)                               \
    a += __shfl_xor_sync(0xffffffffu, a, 16);             \
    b += __shfl_xor_sync(0xffffffffu, b, 16);             \
    a += __shfl_xor_sync(0xffffffffu, a, 8);              \
    b += __shfl_xor_sync(0xffffffffu, b, 8);              \
    a += __shfl_xor_sync(0xffffffffu, a, 4);              \
    b += __shfl_xor_sync(0xffffffffu, b, 4);              \
    a += __shfl_xor_sync(0xffffffffu, a, 2);              \
    b += __shfl_xor_sync(0xffffffffu, b, 2);              \
    a += __shfl_xor_sync(0xffffffffu, a, 1);              \
    b += __shfl_xor_sync(0xffffffffu, b, 1);

#define WARP_RED_SUM4(a, b, c, d)                         \
    a += __shfl_xor_sync(0xffffffffu, a, 16);             \
    b += __shfl_xor_sync(0xffffffffu, b, 16);             \
    c += __shfl_xor_sync(0xffffffffu, c, 16);             \
    d += __shfl_xor_sync(0xffffffffu, d, 16);             \
    a += __shfl_xor_sync(0xffffffffu, a, 8);              \
    b += __shfl_xor_sync(0xffffffffu, b, 8);              \
    c += __shfl_xor_sync(0xffffffffu, c, 8);              \
    d += __shfl_xor_sync(0xffffffffu, d, 8);              \
    a += __shfl_xor_sync(0xffffffffu, a, 4);              \
    b += __shfl_xor_sync(0xffffffffu, b, 4);              \
    c += __shfl_xor_sync(0xffffffffu, c, 4);              \
    d += __shfl_xor_sync(0xffffffffu, d, 4);              \
    a += __shfl_xor_sync(0xffffffffu, a, 2);              \
    b += __shfl_xor_sync(0xffffffffu, b, 2);              \
    c += __shfl_xor_sync(0xffffffffu, c, 2);              \
    d += __shfl_xor_sync(0xffffffffu, d, 2);              \
    a += __shfl_xor_sync(0xffffffffu, a, 1);              \
    b += __shfl_xor_sync(0xffffffffu, b, 1);              \
    c += __shfl_xor_sync(0xffffffffu, c, 1);              \
    d += __shfl_xor_sync(0xffffffffu, d, 1);

__device__ __forceinline__ float dot128(float4 a, float4 b) {
    return fmaf(a.x, b.x, fmaf(a.y, b.y, fmaf(a.z, b.z, a.w * b.w)));
}

// Online softmax update of (m, l, o) with score p and value row v.
#define ONLINE_UPDATE(p, v)                               \
    {                                                     \
        float mn = fmaxf(m, p);                           \
        float cc = __expf(m - mn);                        \
        float ee = __expf(p - mn);                        \
        l = fmaf(l, cc, ee);                              \
        o.x = fmaf(o.x, cc, ee * (v).x);                  \
        o.y = fmaf(o.y, cc, ee * (v).y);                  \
        o.z = fmaf(o.z, cc, ee * (v).z);                  \
        o.w = fmaf(o.w, cc, ee * (v).w);                  \
        m = mn;                                           \
    }

// ---------------------------------------------------------------------------
// Setup: (a) normalize `lengths` to int32 with int32/int64 auto-detect
// (int64 values < 512 have all-zero odd int32 words; genuine random int32
// data in [0,512) has P(all 1024 odd words zero) = (1/512)^1024 ~ 0),
// (b) counting-sort rows by DESCENDING length into g_perm (longest rows
// scheduled first -> no straggler tail). Parallel shfl-based block scan.
// ---------------------------------------------------------------------------
__global__ __launch_bounds__(1024) void setup_kernel(const int* __restrict__ Lraw) {
    __shared__ int cnt[LSZ];
    __shared__ int wsum[16];
    __shared__ int s_any;
    int tid  = threadIdx.x;                 // single block, 1024 threads
    int lane = tid & 31;
    if (tid == 0) s_any = 0;
    if (tid < LSZ) cnt[tid] = 0;
    __syncthreads();
    if (Lraw[2 * tid + 1] != 0) s_any = 1;  // benign race
    __syncthreads();
    int l0, l1;
    if (s_any == 0) {                       // int64 layout
        const long long* L64 = (const long long*)Lraw;
        l0 = (int)L64[2 * tid];
        l1 = (int)L64[2 * tid + 1];
    } else {                                // int32 layout
        l0 = Lraw[2 * tid];
        l1 = Lraw[2 * tid + 1];
    }
    g_len[2 * tid]     = l0;
    g_len[2 * tid + 1] = l1;
    atomicAdd(&cnt[l0], 1);
    atomicAdd(&cnt[l1], 1);
    __syncthreads();

    // Descending exclusive scan: thread r (r<512) owns length l = 511-r.
    int val = 0, incl = 0;
    if (tid < LSZ) {
        val  = cnt[LSZ - 1 - tid];
        incl = val;
        #pragma unroll
        for (int d = 1; d < 32; d <<= 1) {
            int t = __shfl_up_sync(0xffffffffu, incl, d);
            if (lane >= d) incl += t;
        }
        if (lane == 31) wsum[tid >> 5] = incl;
    }
    __syncthreads();
    if (tid < 16) {
        int w = wsum[tid];
        int wi = w;
        #pragma unroll
        for (int d = 1; d < 16; d <<= 1) {
            int t = __shfl_up_sync(0x0000ffffu, wi, d);
            if (tid >= d) wi += t;
        }
        wsum[tid] = wi - w;                 // exclusive warp offsets
    }
    __syncthreads();
    if (tid < LSZ) cnt[LSZ - 1 - tid] = (incl - val) + wsum[tid >> 5];
    __syncthreads();

    int p0 = atomicAdd(&cnt[l0], 1); g_perm[p0] = 2 * tid;
    int p1 = atomicAdd(&cnt[l1], 1); g_perm[p1] = 2 * tid + 1;
}

// ---------------------------------------------------------------------------
// Fused single-pass kernel: per-CTA q/k/v projection, then ONLINE softmax
// attention streaming K and V together over the LIVE suffix [512-len, 512).
// Each warp keeps running (m, l, o); one merge at the end. No score array,
// no block softmax, one barrier between the loop and the epilogue.
// ---------------------------------------------------------------------------
__global__ __launch_bounds__(256) void attn_kernel(
    const float* __restrict__ x,
    const float* __restrict__ K, const float* __restrict__ V,
    const float* __restrict__ Wq, const float* __restrict__ bq,
    const float* __restrict__ Wk, const float* __restrict__ bk,
    const float* __restrict__ Wv, const float* __restrict__ bv,
    float* __restrict__ out)
{
    __shared__ __align__(16) float xs[DSZ];
    __shared__ __align__(16) float qs[DSZ];
    __shared__ __align__(16) float ks[DSZ];
    __shared__ __align__(16) float vs[DSZ];
    __shared__ __align__(16) float s_part[8][DSZ];
    __shared__ float red_m[8];
    __shared__ float red_l[8];

    int tid  = threadIdx.x;
    int lane = tid & 31;
    int wid  = tid >> 5;
    int b    = g_perm[blockIdx.x];
    int len  = g_len[b];                // 0 .. 511
    int j0   = LSZ - len;
    const float inv_sqrt_d = 0.08838834764831845f;   // 1/sqrt(128)

    if (tid < 32) ((float4*)xs)[tid] = ((const float4*)(x + (size_t)b * DSZ))[tid];
    __syncthreads();

    // ---- Projection: q[d] = dot(Wq[d,:], x) + bq[d] (same for k,v).
    {
        float4 xv = ((const float4*)xs)[lane];
        #pragma unroll
        for (int mm = 0; mm < 3; ++mm) {
            const float* W    = (mm == 0) ? Wq : ((mm == 1) ? Wk : Wv);
            const float* bias = (mm == 0) ? bq : ((mm == 1) ? bk : bv);
            float* dst        = (mm == 0) ? qs : ((mm == 1) ? ks : vs);
            #pragma unroll
            for (int j = 0; j < 4; ++j) {
                int d0 = wid + 32 * j;
                float4 w0 = ((const float4*)(W + (d0     ) * DSZ))[lane];
                float4 w1 = ((const float4*)(W + (d0 +  8) * DSZ))[lane];
                float4 w2 = ((const float4*)(W + (d0 + 16) * DSZ))[lane];
                float4 w3 = ((const float4*)(W + (d0 + 24) * DSZ))[lane];
                float p0 = dot128(w0, xv);
                float p1 = dot128(w1, xv);
                float p2 = dot128(w2, xv);
                float p3 = dot128(w3, xv);
                WARP_RED_SUM4(p0, p1, p2, p3);
                if (lane == 0) {
                    dst[d0]      = p0 + bias[d0];
                    dst[d0 +  8] = p1 + bias[d0 + 8];
                    dst[d0 + 16] = p2 + bias[d0 + 16];
                    dst[d0 + 24] = p3 + bias[d0 + 24];
                }
            }
        }
    }
    __syncthreads();

    // ---- Single streaming pass with online softmax. Warp w owns rows
    // i = w + 8t of the live suffix; the new pushed entry goes to warp len&7.
    size_t base = (size_t)b * LSZ * DSZ;
    const float* Kb = K + base + (size_t)j0 * DSZ;
    const float* Vb = V + base + (size_t)j0 * DSZ;

    float4 qv = ((const float4*)qs)[lane];
    float  m  = -3.4e38f;
    float  l  = 0.0f;
    float4 o  = make_float4(0.f, 0.f, 0.f, 0.f);

    if (wid == (len & 7)) {              // new entry first (order irrelevant)
        float4 kn = ((const float4*)ks)[lane];
        float4 vn = ((const float4*)vs)[lane];
        float p = dot128(kn, qv);
        WARP_RED_SUM(p);
        p *= inv_sqrt_d;
        m = p; l = 1.0f;                 // first online step closed-form
        o = vn;
    }

    int nr = (len > wid) ? ((len - wid + 7) >> 3) : 0;   // rows i = wid + 8t
    const float* Kw = Kb + (size_t)wid * DSZ;
    const float* Vw = Vb + (size_t)wid * DSZ;
    int t = 0;
    for (; t + 1 < nr; t += 2) {         // 2 rows/iter, 4 loads front-batched
        size_t off0 = (size_t)(8 * t) * DSZ;
        float4 k0 = ((const float4*)(Kw + off0))[lane];
        float4 k1 = ((const float4*)(Kw + off0 + 8 * DSZ))[lane];
        float4 v0 = ((const float4*)(Vw + off0))[lane];
        float4 v1 = ((const float4*)(Vw + off0 + 8 * DSZ))[lane];
        float p0 = dot128(k0, qv);
        float p1 = dot128(k1, qv);
        WARP_RED_SUM2(p0, p1);
        p0 *= inv_sqrt_d;
        p1 *= inv_sqrt_d;
        ONLINE_UPDATE(p0, v0);
        ONLINE_UPDATE(p1, v1);
    }
    if (t < nr) {
        size_t off0 = (size_t)(8 * t) * DSZ;
        float4 k0 = ((const float4*)(Kw + off0))[lane];
        float4 v0 = ((const float4*)(Vw + off0))[lane];
        float p0 = dot128(k0, qv);
        WARP_RED_SUM(p0);
        p0 *= inv_sqrt_d;
        ONLINE_UPDATE(p0, v0);
    }

    // ---- Merge the 8 per-warp (m, l, o) triples.
    if (lane == 0) red_m[wid] = m;
    __syncthreads();
    float M = red_m[0];
    #pragma unroll
    for (int w = 1; w < 8; ++w) M = fmaxf(M, red_m[w]);
    float f = __expf(m - M);             // 0 for warps that saw no rows
    if (lane == 0) red_l[wid] = l * f;
    o.x *= f; o.y *= f; o.z *= f; o.w *= f;
    ((float4*)&s_part[wid][0])[lane] = o;
    __syncthreads();

    if (tid < DSZ) {
        float L = red_l[0];
        #pragma unroll
        for (int w = 1; w < 8; ++w) L += red_l[w];
        float s = 0.0f;
        #pragma unroll
        for (int w = 0; w < 8; ++w) s += s_part[w][tid];
        out[(size_t)b * DSZ + tid] = s / L;
    }
}

// ---------------------------------------------------------------------------
extern "C" void kernel_launch(void* const* d_in, const int* in_sizes, int n_in,
                              void* d_out, int out_size) {
    const float* inputs      = (const float*)d_in[0];
    const float* prev_keys   = (const float*)d_in[1];
    const float* prev_values = (const float*)d_in[2];
    const float* Wq          = (const float*)d_in[3];
    const float* bq          = (const float*)d_in[4];
    const float* Wk          = (const float*)d_in[5];
    const float* bk          = (const float*)d_in[6];
    const float* Wv          = (const float*)d_in[7];
    const float* bv          = (const float*)d_in[8];
    const int*   lengths_raw = (const int*)d_in[9];
    float* out               = (float*)d_out;

    setup_kernel<<<1, 1024>>>(lengths_raw);
    attn_kernel<<<BSZ, 256>>>(inputs, prev_keys, prev_values,
                              Wq, bq, Wk, bk, Wv, bv, out);
}

// round 8
// speedup vs baseline: 1.0478x; 1.0220x over previous
#include <cuda_runtime.h>
#include <cstdint>

#define BSZ 2048
#define LSZ 512
#define DSZ 128
#define TILE 16          // rows per pipeline stage (8KB K + 8KB V)
#define NST  3           // pipeline depth

__device__ int g_len[BSZ];     // normalized lengths (dtype auto-detected)
__device__ int g_perm[BSZ];    // batch rows sorted by descending length

#define WARP_RED_SUM(p)                                   \
    p += __shfl_xor_sync(0xffffffffu, p, 16);             \
    p += __shfl_xor_sync(0xffffffffu, p, 8);              \
    p += __shfl_xor_sync(0xffffffffu, p, 4);              \
    p += __shfl_xor_sync(0xffffffffu, p, 2);              \
    p += __shfl_xor_sync(0xffffffffu, p, 1);

#define WARP_RED_SUM2(a, b)                               \
    a += __shfl_xor_sync(0xffffffffu, a, 16);             \
    b += __shfl_xor_sync(0xffffffffu, b, 16);             \
    a += __shfl_xor_sync(0xffffffffu, a, 8);              \
    b += __shfl_xor_sync(0xffffffffu, b, 8);              \
    a += __shfl_xor_sync(0xffffffffu, a, 4);              \
    b += __shfl_xor_sync(0xffffffffu, b, 4);              \
    a += __shfl_xor_sync(0xffffffffu, a, 2);              \
    b += __shfl_xor_sync(0xffffffffu, b, 2);              \
    a += __shfl_xor_sync(0xffffffffu, a, 1);              \
    b += __shfl_xor_sync(0xffffffffu, b, 1);

#define WARP_RED_SUM4(a, b, c, d)                         \
    WARP_RED_SUM2(a, b)                                   \
    WARP_RED_SUM2(c, d)

__device__ __forceinline__ float dot128(float4 a, float4 b) {
    return fmaf(a.x, b.x, fmaf(a.y, b.y, fmaf(a.z, b.z, a.w * b.w)));
}

// Online softmax update of (m, l, o) with score p and value row v.
#define ONLINE_UPDATE(p, v)                               \
    {                                                     \
        float mn = fmaxf(m, p);                           \
        float cc = __expf(m - mn);                        \
        float ee = __expf(p - mn);                        \
        l = fmaf(l, cc, ee);                              \
        o.x = fmaf(o.x, cc, ee * (v).x);                  \
        o.y = fmaf(o.y, cc, ee * (v).y);                  \
        o.z = fmaf(o.z, cc, ee * (v).z);                  \
        o.w = fmaf(o.w, cc, ee * (v).w);                  \
        m = mn;                                           \
    }

// ---- bulk-async (UBLKCP) + mbarrier primitives --------------------------
__device__ __forceinline__ void mbar_init(uint32_t mbar, uint32_t count) {
    asm volatile("mbarrier.init.shared.b64 [%0], %1;" :: "r"(mbar), "r"(count) : "memory");
}
__device__ __forceinline__ void mbar_expect_tx(uint32_t mbar, uint32_t tx) {
    asm volatile("mbarrier.arrive.expect_tx.shared.b64 _, [%0], %1;"
                 :: "r"(mbar), "r"(tx) : "memory");
}
__device__ __forceinline__ void bulk_g2s(uint32_t dst, const void* src,
                                         uint32_t bytes, uint32_t mbar) {
    asm volatile("cp.async.bulk.shared::cta.global.mbarrier::complete_tx::bytes "
                 "[%0], [%1], %2, [%3];"
                 :: "r"(dst), "l"(src), "r"(bytes), "r"(mbar) : "memory");
}
__device__ __forceinline__ void mbar_wait(uint32_t mbar, uint32_t parity) {
    uint32_t done;
    do {
        asm volatile(
            "{\n\t.reg .pred p;\n\t"
            "mbarrier.try_wait.parity.acquire.cta.shared::cta.b64 p, [%1], %2, 0x989680;\n\t"
            "selp.b32 %0, 1, 0, p;\n\t}"
            : "=r"(done) : "r"(mbar), "r"(parity) : "memory");
    } while (!done);
}

// ---------------------------------------------------------------------------
// Setup: (a) normalize `lengths` to int32 with int32/int64 auto-detect
// (int64 values < 512 have all-zero odd int32 words), (b) counting-sort rows
// by DESCENDING length into g_perm. Parallel shfl-based block scan.
// ---------------------------------------------------------------------------
__global__ __launch_bounds__(1024) void setup_kernel(const int* __restrict__ Lraw) {
    __shared__ int cnt[LSZ];
    __shared__ int wsum[16];
    __shared__ int s_any;
    int tid  = threadIdx.x;                 // single block, 1024 threads
    int lane = tid & 31;
    if (tid == 0) s_any = 0;
    if (tid < LSZ) cnt[tid] = 0;
    __syncthreads();
    if (Lraw[2 * tid + 1] != 0) s_any = 1;  // benign race
    __syncthreads();
    int l0, l1;
    if (s_any == 0) {                       // int64 layout
        const long long* L64 = (const long long*)Lraw;
        l0 = (int)L64[2 * tid];
        l1 = (int)L64[2 * tid + 1];
    } else {                                // int32 layout
        l0 = Lraw[2 * tid];
        l1 = Lraw[2 * tid + 1];
    }
    g_len[2 * tid]     = l0;
    g_len[2 * tid + 1] = l1;
    atomicAdd(&cnt[l0], 1);
    atomicAdd(&cnt[l1], 1);
    __syncthreads();

    int val = 0, incl = 0;
    if (tid < LSZ) {                        // descending exclusive scan
        val  = cnt[LSZ - 1 - tid];
        incl = val;
        #pragma unroll
        for (int d = 1; d < 32; d <<= 1) {
            int t = __shfl_up_sync(0xffffffffu, incl, d);
            if (lane >= d) incl += t;
        }
        if (lane == 31) wsum[tid >> 5] = incl;
    }
    __syncthreads();
    if (tid < 16) {
        int w = wsum[tid];
        int wi = w;
        #pragma unroll
        for (int d = 1; d < 16; d <<= 1) {
            int t = __shfl_up_sync(0x0000ffffu, wi, d);
            if (tid >= d) wi += t;
        }
        wsum[tid] = wi - w;
    }
    __syncthreads();
    if (tid < LSZ) cnt[LSZ - 1 - tid] = (incl - val) + wsum[tid >> 5];
    __syncthreads();

    int p0 = atomicAdd(&cnt[l0], 1); g_perm[p0] = 2 * tid;
    int p1 = atomicAdd(&cnt[l1], 1); g_perm[p1] = 2 * tid + 1;
}

// ---------------------------------------------------------------------------
// Fused kernel: q/k/v projection + online-softmax attention, with K/V of the
// LIVE suffix streamed through a 3-stage cp.async.bulk pipeline so memory
// stays in flight independent of warp compute latency.
// ---------------------------------------------------------------------------
__global__ __launch_bounds__(256) void attn_kernel(
    const float* __restrict__ x,
    const float* __restrict__ K, const float* __restrict__ V,
    const float* __restrict__ Wq, const float* __restrict__ bq,
    const float* __restrict__ Wk, const float* __restrict__ bk,
    const float* __restrict__ Wv, const float* __restrict__ bv,
    float* __restrict__ out)
{
    __shared__ __align__(1024) float kbuf[NST][TILE][DSZ];   // 24KB
    __shared__ __align__(1024) float vbuf[NST][TILE][DSZ];   // 24KB
    __shared__ __align__(16) float xs[DSZ];
    __shared__ __align__(16) float qs[DSZ];
    __shared__ __align__(16) float ks[DSZ];
    __shared__ __align__(16) float vs[DSZ];
    __shared__ __align__(16) float s_part[8][DSZ];
    __shared__ float red_m[8];
    __shared__ float red_l[8];
    __shared__ __align__(8) unsigned long long mbar[NST];

    int tid  = threadIdx.x;
    int lane = tid & 31;
    int wid  = tid >> 5;
    int b    = g_perm[blockIdx.x];
    int len  = g_len[b];                // 0 .. 511
    int j0   = LSZ - len;
    const float inv_sqrt_d = 0.08838834764831845f;   // 1/sqrt(128)

    size_t base = (size_t)b * LSZ * DSZ;
    const float* Ksuf = K + base + (size_t)j0 * DSZ;    // contiguous len*512B
    const float* Vsuf = V + base + (size_t)j0 * DSZ;
    int ntiles = (len + TILE - 1) / TILE;

    uint32_t mb0 = (uint32_t)__cvta_generic_to_shared(&mbar[0]);
    uint32_t kb0 = (uint32_t)__cvta_generic_to_shared(&kbuf[0][0][0]);
    uint32_t vb0 = (uint32_t)__cvta_generic_to_shared(&vbuf[0][0][0]);

    if (tid == 0) {
        #pragma unroll
        for (int s = 0; s < NST; ++s) mbar_init(mb0 + 8 * s, 1);
        asm volatile("fence.proxy.async.shared::cta;" ::: "memory");
    }
    if (tid < 32) ((float4*)xs)[tid] = ((const float4*)(x + (size_t)b * DSZ))[tid];
    __syncthreads();

    // ---- Prologue: fill the pipeline (overlaps with projection below).
    if (tid == 0) {
        #pragma unroll
        for (int s = 0; s < NST; ++s) {
            if (s < ntiles) {
                int rows = min(TILE, len - s * TILE);
                uint32_t bytes = (uint32_t)rows * DSZ * 4;
                mbar_expect_tx(mb0 + 8 * s, 2 * bytes);
                bulk_g2s(kb0 + s * (TILE * DSZ * 4), Ksuf + (size_t)s * TILE * DSZ,
                         bytes, mb0 + 8 * s);
                bulk_g2s(vb0 + s * (TILE * DSZ * 4), Vsuf + (size_t)s * TILE * DSZ,
                         bytes, mb0 + 8 * s);
            }
        }
    }

    // ---- Projection: q[d] = dot(Wq[d,:], x) + bq[d] (same for k,v).
    {
        float4 xv = ((const float4*)xs)[lane];
        #pragma unroll
        for (int mm = 0; mm < 3; ++mm) {
            const float* W    = (mm == 0) ? Wq : ((mm == 1) ? Wk : Wv);
            const float* bias = (mm == 0) ? bq : ((mm == 1) ? bk : bv);
            float* dst        = (mm == 0) ? qs : ((mm == 1) ? ks : vs);
            #pragma unroll
            for (int j = 0; j < 4; ++j) {
                int d0 = wid + 32 * j;
                float4 w0 = ((const float4*)(W + (d0     ) * DSZ))[lane];
                float4 w1 = ((const float4*)(W + (d0 +  8) * DSZ))[lane];
                float4 w2 = ((const float4*)(W + (d0 + 16) * DSZ))[lane];
                float4 w3 = ((const float4*)(W + (d0 + 24) * DSZ))[lane];
                float p0 = dot128(w0, xv);
                float p1 = dot128(w1, xv);
                float p2 = dot128(w2, xv);
                float p3 = dot128(w3, xv);
                WARP_RED_SUM4(p0, p1, p2, p3);
                if (lane == 0) {
                    dst[d0]      = p0 + bias[d0];
                    dst[d0 +  8] = p1 + bias[d0 + 8];
                    dst[d0 + 16] = p2 + bias[d0 + 16];
                    dst[d0 + 24] = p3 + bias[d0 + 24];
                }
            }
        }
    }
    __syncthreads();

    // ---- Online-softmax stream over pipeline tiles.
    float4 qv = ((const float4*)qs)[lane];
    float  m  = -3.4e38f;
    float  l  = 0.0f;
    float4 o  = make_float4(0.f, 0.f, 0.f, 0.f);

    if (wid == (len & 7)) {              // new pushed entry (order irrelevant)
        float4 kn = ((const float4*)ks)[lane];
        float4 vn = ((const float4*)vs)[lane];
        float p = dot128(kn, qv);
        WARP_RED_SUM(p);
        p *= inv_sqrt_d;
        m = p; l = 1.0f;
        o = vn;
    }

    int s = 0, phase = 0;                // stage index + parity, kept in regs
    for (int t = 0; t < ntiles; ++t) {
        mbar_wait(mb0 + 8 * s, phase);
        int rows = min(TILE, len - t * TILE);
        int  r1v = wid + 8 < rows;       // row wid always valid unless tail
        int  r0v = wid < rows;
        float4 k0, v0, k1, v1;
        float p0 = 0.0f, p1 = 0.0f;
        if (r0v) {
            k0 = *(const float4*)&kbuf[s][wid][lane * 4];
            v0 = *(const float4*)&vbuf[s][wid][lane * 4];
            p0 = dot128(k0, qv);
        }
        if (r1v) {
            k1 = *(const float4*)&kbuf[s][wid + 8][lane * 4];
            v1 = *(const float4*)&vbuf[s][wid + 8][lane * 4];
            p1 = dot128(k1, qv);
        }
        WARP_RED_SUM2(p0, p1);
        if (r0v) { p0 *= inv_sqrt_d; ONLINE_UPDATE(p0, v0); }
        if (r1v) { p1 *= inv_sqrt_d; ONLINE_UPDATE(p1, v1); }
        __syncthreads();                 // everyone done reading stage s
        int tn = t + NST;
        if (tid == 0 && tn < ntiles) {   // refill stage s with tile tn
            int rows2 = min(TILE, len - tn * TILE);
            uint32_t bytes = (uint32_t)rows2 * DSZ * 4;
            mbar_expect_tx(mb0 + 8 * s, 2 * bytes);
            bulk_g2s(kb0 + s * (TILE * DSZ * 4), Ksuf + (size_t)tn * TILE * DSZ,
                     bytes, mb0 + 8 * s);
            bulk_g2s(vb0 + s * (TILE * DSZ * 4), Vsuf + (size_t)tn * TILE * DSZ,
                     bytes, mb0 + 8 * s);
        }
        if (++s == NST) { s = 0; phase ^= 1; }
    }

    // ---- Merge the 8 per-warp (m, l, o) triples.
    if (lane == 0) red_m[wid] = m;
    __syncthreads();
    float M = red_m[0];
    #pragma unroll
    for (int w = 1; w < 8; ++w) M = fmaxf(M, red_m[w]);
    float f = __expf(m - M);             // 0 for warps that saw no rows
    if (lane == 0) red_l[wid] = l * f;
    o.x *= f; o.y *= f; o.z *= f; o.w *= f;
    ((float4*)&s_part[wid][0])[lane] = o;
    __syncthreads();

    if (tid < DSZ) {
        float L = red_l[0];
        #pragma unroll
        for (int w = 1; w < 8; ++w) L += red_l[w];
        float sm = 0.0f;
        #pragma unroll
        for (int w = 0; w < 8; ++w) sm += s_part[w][tid];
        out[(size_t)b * DSZ + tid] = sm / L;
    }
}

// ---------------------------------------------------------------------------
extern "C" void kernel_launch(void* const* d_in, const int* in_sizes, int n_in,
                              void* d_out, int out_size) {
    const float* inputs      = (const float*)d_in[0];
    const float* prev_keys   = (const float*)d_in[1];
    const float* prev_values = (const float*)d_in[2];
    const float* Wq          = (const float*)d_in[3];
    const float* bq          = (const float*)d_in[4];
    const float* Wk          = (const float*)d_in[5];
    const float* bk          = (const float*)d_in[6];
    const float* Wv          = (const float*)d_in[7];
    const float* bv          = (const float*)d_in[8];
    const int*   lengths_raw = (const int*)d_in[9];
    float* out               = (float*)d_out;

    setup_kernel<<<1, 1024>>>(lengths_raw);
    attn_kernel<<<BSZ, 256>>>(inputs, prev_keys, prev_values,
                              Wq, bq, Wk, bk, Wv, bv, out);
}